// round 3
// baseline (speedup 1.0000x reference)
#include <cuda_runtime.h>
#include <cstdint>
#include <cstddef>

#define ITERS   50
#define NCAP    200000
#define MCAP    256
#define BLK     512
#define NWARP   (BLK / 32)

// Ping-pong survivor lists: {x, y, z, original_index_as_bits}
// Each array: 256 * 200000 * 16B = 1.6384e9 bytes (< 2^31 per symbol).
__device__ float4 g_listA[MCAP][NCAP];
__device__ float4 g_listB[MCAP][NCAP];

__device__ __forceinline__ void argmin_merge(float& bd, int& bi, float d, int i)
{
    if (d < bd || (d == bd && i < bi)) { bd = d; bi = i; }
}

__global__ __launch_bounds__(BLK, 2)
void cpc_kernel(const float* __restrict__ pc, const float* __restrict__ tg,
                float* __restrict__ out, int N, int M)
{
    const int m    = blockIdx.x;
    const int tid  = threadIdx.x;
    const int lane = tid & 31;
    const int warp = tid >> 5;

    __shared__ float s_rd[NWARP];
    __shared__ int   s_ri[NWARP];
    __shared__ float s_pl[4];     // a0, a1, a2, b
    __shared__ int   s_cursor;
    __shared__ int   s_done;

    const float tx = tg[3 * m + 0];
    const float ty = tg[3 * m + 1];
    const float tz = tg[3 * m + 2];
    // t2 = sum(targets*targets, axis=1): plain mul + sequential add (XLA reduce)
    const float t2 = __fadd_rn(__fadd_rn(__fmul_rn(tx, tx), __fmul_rn(ty, ty)),
                               __fmul_rn(tz, tz));

    float a0 = 0.f, a1 = 0.f, a2 = 0.f, bpl = 0.f;   // current plane
    int   srcBuf = -1;                               // -1: raw pointcloud
    int   count  = N;

    float* outA = out;                                  // [ITERS][M][3]
    float* outB = out + (size_t)ITERS * (size_t)M * 3;  // [ITERS][M]

    for (int iter = 0; iter < ITERS; ++iter) {
        if (tid == 0) { s_cursor = 0; s_done = 0; }
        __syncthreads();

        float bd = __int_as_float(0x7f800000);  // +inf
        int   bi = 0x7fffffff;

        const bool havePlane = (iter >= 1);
        float4* dst = nullptr;
        if (iter >= 1) dst = (iter & 1) ? g_listB[m] : g_listA[m];

        if (srcBuf < 0) {
            // Source = raw pointcloud (iterations 0 and 1)
            for (int base = warp * 128; base < count; base += NWARP * 128) {
                float px[4], py[4], pz[4];
                int   ix[4];
                unsigned kmask[4];
                int tot = 0;
                #pragma unroll
                for (int s = 0; s < 4; ++s) {
                    const int i = base + s * 32 + lane;
                    const bool valid = (i < count);
                    float x = 0.f, y = 0.f, z = 0.f;
                    if (valid) { x = pc[3 * i]; y = pc[3 * i + 1]; z = pc[3 * i + 2]; }
                    bool keep = valid;
                    if (keep && havePlane) {
                        // dot = a @ p (FMA chain, Eigen-style), separated iff (dot - b) >= -1e-6
                        const float da = __fmaf_rn(a2, z, __fmaf_rn(a1, y, __fmul_rn(a0, x)));
                        keep = (__fadd_rn(da, -bpl) < -1e-6f);
                    }
                    px[s] = x; py[s] = y; pz[s] = z; ix[s] = i;
                    kmask[s] = __ballot_sync(0xffffffffu, keep);
                    tot += __popc(kmask[s]);
                    if (keep) {
                        const float p2 = __fadd_rn(__fadd_rn(__fmul_rn(x, x), __fmul_rn(y, y)),
                                                   __fmul_rn(z, z));
                        const float dt = __fmaf_rn(tz, z, __fmaf_rn(ty, y, __fmul_rn(tx, x)));
                        const float d2 = __fadd_rn(__fadd_rn(t2, p2), __fmul_rn(-2.f, dt));
                        argmin_merge(bd, bi, d2, i);
                    }
                }
                if (dst) {
                    int wbase = 0;
                    if (lane == 0 && tot) wbase = atomicAdd(&s_cursor, tot);
                    wbase = __shfl_sync(0xffffffffu, wbase, 0);
                    int off = 0;
                    #pragma unroll
                    for (int s = 0; s < 4; ++s) {
                        const unsigned mk = kmask[s];
                        if (mk & (1u << lane)) {
                            const int pos = wbase + off + __popc(mk & ((1u << lane) - 1u));
                            dst[pos] = make_float4(px[s], py[s], pz[s], __int_as_float(ix[s]));
                        }
                        off += __popc(mk);
                    }
                }
            }
        } else {
            // Source = compacted list
            const float4* src = srcBuf ? g_listB[m] : g_listA[m];
            for (int base = warp * 128; base < count; base += NWARP * 128) {
                float px[4], py[4], pz[4];
                int   ix[4];
                unsigned kmask[4];
                int tot = 0;
                #pragma unroll
                for (int s = 0; s < 4; ++s) {
                    const int i = base + s * 32 + lane;
                    const bool valid = (i < count);
                    float x = 0.f, y = 0.f, z = 0.f;
                    int idx = 0;
                    if (valid) {
                        const float4 v = src[i];
                        x = v.x; y = v.y; z = v.z;
                        idx = __float_as_int(v.w);
                    }
                    bool keep = valid;
                    if (keep) {
                        const float da = __fmaf_rn(a2, z, __fmaf_rn(a1, y, __fmul_rn(a0, x)));
                        keep = (__fadd_rn(da, -bpl) < -1e-6f);
                    }
                    px[s] = x; py[s] = y; pz[s] = z; ix[s] = idx;
                    kmask[s] = __ballot_sync(0xffffffffu, keep);
                    tot += __popc(kmask[s]);
                    if (keep) {
                        const float p2 = __fadd_rn(__fadd_rn(__fmul_rn(x, x), __fmul_rn(y, y)),
                                                   __fmul_rn(z, z));
                        const float dt = __fmaf_rn(tz, z, __fmaf_rn(ty, y, __fmul_rn(tx, x)));
                        const float d2 = __fadd_rn(__fadd_rn(t2, p2), __fmul_rn(-2.f, dt));
                        argmin_merge(bd, bi, d2, idx);
                    }
                }
                {
                    int wbase = 0;
                    if (lane == 0 && tot) wbase = atomicAdd(&s_cursor, tot);
                    wbase = __shfl_sync(0xffffffffu, wbase, 0);
                    int off = 0;
                    #pragma unroll
                    for (int s = 0; s < 4; ++s) {
                        const unsigned mk = kmask[s];
                        if (mk & (1u << lane)) {
                            const int pos = wbase + off + __popc(mk & ((1u << lane) - 1u));
                            dst[pos] = make_float4(px[s], py[s], pz[s], __int_as_float(ix[s]));
                        }
                        off += __popc(mk);
                    }
                }
            }
        }
        __syncthreads();

        // Block argmin reduction (warp shuffle tree, lowest-original-index tie-break)
        #pragma unroll
        for (int o = 16; o; o >>= 1) {
            const float od = __shfl_down_sync(0xffffffffu, bd, o);
            const int   oi = __shfl_down_sync(0xffffffffu, bi, o);
            argmin_merge(bd, bi, od, oi);
        }
        if (lane == 0) { s_rd[warp] = bd; s_ri[warp] = bi; }
        __syncthreads();

        if (tid < 32) {
            bd = (lane < NWARP) ? s_rd[lane] : __int_as_float(0x7f800000);
            bi = (lane < NWARP) ? s_ri[lane] : 0x7fffffff;
            #pragma unroll
            for (int o = 16; o; o >>= 1) {
                const float od = __shfl_down_sync(0xffffffffu, bd, o);
                const int   oi = __shfl_down_sync(0xffffffffu, bi, o);
                argmin_merge(bd, bi, od, oi);
            }
            if (lane == 0) {
                const bool empty = (bi == 0x7fffffff);   // all-inf -> jnp.argmin = 0
                const int  ci = empty ? 0 : bi;
                const float cx = pc[3 * ci], cy = pc[3 * ci + 1], cz = pc[3 * ci + 2];
                const float dx = __fadd_rn(cx, -tx);
                const float dy = __fadd_rn(cy, -ty);
                const float dz = __fadd_rn(cz, -tz);
                const float n2 = __fadd_rn(__fadd_rn(__fmul_rn(dx, dx), __fmul_rn(dy, dy)),
                                           __fmul_rn(dz, dz));
                const float nrm = __fadd_rn(__fsqrt_rn(n2), 1e-8f);
                const float A0 = __fdiv_rn(dx, nrm);
                const float A1 = __fdiv_rn(dy, nrm);
                const float A2 = __fdiv_rn(dz, nrm);
                const float B  = __fadd_rn(__fadd_rn(__fmul_rn(A0, cx), __fmul_rn(A1, cy)),
                                           __fmul_rn(A2, cz));
                if (!empty) {
                    const size_t oa = (size_t)iter * M * 3 + (size_t)m * 3;
                    outA[oa + 0] = A0; outA[oa + 1] = A1; outA[oa + 2] = A2;
                    outB[(size_t)iter * M + m] = B;
                    s_pl[0] = A0; s_pl[1] = A1; s_pl[2] = A2; s_pl[3] = B;
                } else {
                    // Empty survivor set: (a,b) constant for all remaining iterations.
                    for (int k = iter; k < ITERS; ++k) {
                        const size_t oa = (size_t)k * M * 3 + (size_t)m * 3;
                        outA[oa + 0] = A0; outA[oa + 1] = A1; outA[oa + 2] = A2;
                        outB[(size_t)k * M + m] = B;
                    }
                    s_done = 1;
                }
            }
        }
        __syncthreads();

        if (s_done) break;

        a0 = s_pl[0]; a1 = s_pl[1]; a2 = s_pl[2]; bpl = s_pl[3];
        if (iter >= 1) { srcBuf = iter & 1; count = s_cursor; }
        __syncthreads();   // protect s_cursor / s_done / s_pl against next-iter reset
    }
}

extern "C" void kernel_launch(void* const* d_in, const int* in_sizes, int n_in,
                              void* d_out, int out_size)
{
    const float* pc = (const float*)d_in[0];
    const float* tg = (const float*)d_in[1];
    int szp = in_sizes[0], szt = in_sizes[1];
    if (szp < szt) {  // defensive: pointcloud is the larger input
        const float* t = pc; pc = tg; tg = t;
        int s = szp; szp = szt; szt = s;
    }
    const int N = szp / 3;
    const int M = szt / 3;
    cpc_kernel<<<M, BLK>>>(pc, tg, (float*)d_out, N, M);
}

// round 4
// speedup vs baseline: 1.2973x; 1.2973x over previous
#include <cuda_runtime.h>
#include <cooperative_groups.h>
#include <cstdint>
#include <cstddef>

namespace cg = cooperative_groups;

#define ITERS   50
#define NCAP    200000
#define MCAP    256
#define BLK     512
#define NWARP   (BLK / 32)
#define CLUS    2
// Per-rank survivor capacity: ceil(ceil(200000/128)/32)*16 chunks * 128 = 100352
#define REGION  100352

// Ping-pong survivor lists, one region per (target, cluster-rank).
// Each symbol: 256 * 2 * 100352 * 16B = 822,083,584 bytes (< 2^31 per symbol).
__device__ float4 g_listA[MCAP][CLUS][REGION];
__device__ float4 g_listB[MCAP][CLUS][REGION];

__device__ __forceinline__ void argmin_merge(float& bd, int& bi, float d, int i)
{
    if (d < bd || (d == bd && i < bi)) { bd = d; bi = i; }
}

__global__ void __cluster_dims__(CLUS, 1, 1) __launch_bounds__(BLK, 3)
cpc_kernel(const float* __restrict__ pc, const float* __restrict__ tg,
           float* __restrict__ out, int N, int M)
{
    cg::cluster_group cl = cg::this_cluster();
    const int rank = (int)cl.block_rank();
    const int m    = blockIdx.x / CLUS;
    const int tid  = threadIdx.x;
    const int lane = tid & 31;
    const int warp = tid >> 5;

    __shared__ float  s_rd[NWARP];
    __shared__ int    s_ri[NWARP];
    __shared__ float  s_pl[4];      // a0, a1, a2, b
    __shared__ int    s_cursor;
    __shared__ int    s_done;
    __shared__ float2 s_mail[2];    // double-buffered {best_d, best_i bits} mailbox

    const float tx = tg[3 * m + 0];
    const float ty = tg[3 * m + 1];
    const float tz = tg[3 * m + 2];
    // t2 = sum(targets*targets, axis=1): plain mul + sequential add (XLA reduce)
    const float t2 = __fadd_rn(__fadd_rn(__fmul_rn(tx, tx), __fmul_rn(ty, ty)),
                               __fmul_rn(tz, tz));

    float a0 = 0.f, a1 = 0.f, a2 = 0.f, bpl = 0.f;   // current plane
    int   count = N;                                  // elements in my source

    float* outA = out;                                  // [ITERS][M][3]
    float* outB = out + (size_t)ITERS * (size_t)M * 3;  // [ITERS][M]

    for (int iter = 0; iter < ITERS; ++iter) {
        if (tid == 0) { s_cursor = 0; s_done = 0; }
        __syncthreads();

        float bd = __int_as_float(0x7f800000);  // +inf
        int   bi = 0x7fffffff;

        const bool havePlane = (iter >= 1);
        // dst for iter k (k>=1): odd -> B, even -> A. src for k>=2 is the other.
        float4* dst = nullptr;
        if (iter >= 1) dst = (iter & 1) ? g_listB[m][rank] : g_listA[m][rank];

        if (iter < 2) {
            // Source = raw pointcloud; interleaved chunk stripes across cluster ranks.
            for (int base = (warp + rank * NWARP) * 128; base < count;
                 base += CLUS * NWARP * 128) {
                float4   v[4];
                unsigned kmask[4];
                int tot = 0;
                #pragma unroll
                for (int s = 0; s < 4; ++s) {
                    const int i = base + s * 32 + lane;
                    const bool valid = (i < count);
                    float x = 0.f, y = 0.f, z = 0.f;
                    if (valid) { x = pc[3 * i]; y = pc[3 * i + 1]; z = pc[3 * i + 2]; }
                    bool keep = valid;
                    if (keep && havePlane) {
                        const float da = __fmaf_rn(a2, z, __fmaf_rn(a1, y, __fmul_rn(a0, x)));
                        keep = (__fadd_rn(da, -bpl) < -1e-6f);
                    }
                    v[s] = make_float4(x, y, z, __int_as_float(i));
                    kmask[s] = __ballot_sync(0xffffffffu, keep);
                    tot += __popc(kmask[s]);
                    if (keep) {
                        const float p2 = __fadd_rn(__fadd_rn(__fmul_rn(x, x), __fmul_rn(y, y)),
                                                   __fmul_rn(z, z));
                        const float dt = __fmaf_rn(tz, z, __fmaf_rn(ty, y, __fmul_rn(tx, x)));
                        const float d2 = __fadd_rn(__fadd_rn(t2, p2), __fmul_rn(-2.f, dt));
                        argmin_merge(bd, bi, d2, i);
                    }
                }
                if (dst) {
                    int wbase = 0;
                    if (lane == 0 && tot) wbase = atomicAdd(&s_cursor, tot);
                    wbase = __shfl_sync(0xffffffffu, wbase, 0);
                    int off = 0;
                    #pragma unroll
                    for (int s = 0; s < 4; ++s) {
                        const unsigned mk = kmask[s];
                        if (mk & (1u << lane)) {
                            const int pos = wbase + off + __popc(mk & ((1u << lane) - 1u));
                            dst[pos] = v[s];
                        }
                        off += __popc(mk);
                    }
                }
            }
        } else {
            // Source = my rank's compacted list from the previous iteration.
            const float4* src = (iter & 1) ? g_listA[m][rank] : g_listB[m][rank];
            for (int base = warp * 128; base < count; base += NWARP * 128) {
                float4   v[4];
                unsigned kmask[4];
                int tot = 0;
                #pragma unroll
                for (int s = 0; s < 4; ++s) {
                    const int i = base + s * 32 + lane;
                    const bool valid = (i < count);
                    float4 vv = make_float4(0.f, 0.f, 0.f, __int_as_float(0));
                    if (valid) vv = src[i];
                    bool keep = valid;
                    if (keep) {
                        const float da = __fmaf_rn(a2, vv.z,
                                         __fmaf_rn(a1, vv.y, __fmul_rn(a0, vv.x)));
                        keep = (__fadd_rn(da, -bpl) < -1e-6f);
                    }
                    v[s] = vv;
                    kmask[s] = __ballot_sync(0xffffffffu, keep);
                    tot += __popc(kmask[s]);
                    if (keep) {
                        const float p2 = __fadd_rn(__fadd_rn(__fmul_rn(vv.x, vv.x),
                                                             __fmul_rn(vv.y, vv.y)),
                                                   __fmul_rn(vv.z, vv.z));
                        const float dt = __fmaf_rn(tz, vv.z,
                                         __fmaf_rn(ty, vv.y, __fmul_rn(tx, vv.x)));
                        const float d2 = __fadd_rn(__fadd_rn(t2, p2), __fmul_rn(-2.f, dt));
                        argmin_merge(bd, bi, d2, __float_as_int(vv.w));
                    }
                }
                {
                    int wbase = 0;
                    if (lane == 0 && tot) wbase = atomicAdd(&s_cursor, tot);
                    wbase = __shfl_sync(0xffffffffu, wbase, 0);
                    int off = 0;
                    #pragma unroll
                    for (int s = 0; s < 4; ++s) {
                        const unsigned mk = kmask[s];
                        if (mk & (1u << lane)) {
                            const int pos = wbase + off + __popc(mk & ((1u << lane) - 1u));
                            dst[pos] = v[s];
                        }
                        off += __popc(mk);
                    }
                }
            }
        }
        __syncthreads();

        // Block argmin reduction (warp shuffle tree, lowest-original-index tie-break)
        #pragma unroll
        for (int o = 16; o; o >>= 1) {
            const float od = __shfl_down_sync(0xffffffffu, bd, o);
            const int   oi = __shfl_down_sync(0xffffffffu, bi, o);
            argmin_merge(bd, bi, od, oi);
        }
        if (lane == 0) { s_rd[warp] = bd; s_ri[warp] = bi; }
        __syncthreads();

        const int buf = iter & 1;
        if (tid < 32) {
            bd = (lane < NWARP) ? s_rd[lane] : __int_as_float(0x7f800000);
            bi = (lane < NWARP) ? s_ri[lane] : 0x7fffffff;
            #pragma unroll
            for (int o = 16; o; o >>= 1) {
                const float od = __shfl_down_sync(0xffffffffu, bd, o);
                const int   oi = __shfl_down_sync(0xffffffffu, bi, o);
                argmin_merge(bd, bi, od, oi);
            }
            if (lane == 0) s_mail[buf] = make_float2(bd, __int_as_float(bi));
        }

        // Cluster-wide exchange of per-rank argmin. barrier.cluster orders the
        // smem write above against the peer's DSMEM read below. Double-buffered
        // mailbox -> a single cluster.sync per iteration is race-free.
        cl.sync();

        if (tid == 0) {
            const float2 ov = s_mail[buf];
            const float2* pmail = cl.map_shared_rank((const float2*)s_mail, rank ^ 1);
            const float2 pv = pmail[buf];
            float fbd = ov.x;  int fbi = __float_as_int(ov.y);
            argmin_merge(fbd, fbi, pv.x, __float_as_int(pv.y));

            const bool empty = (fbi == 0x7fffffff);   // all-inf -> jnp.argmin = 0
            const int  ci = empty ? 0 : fbi;
            const float cx = pc[3 * ci], cy = pc[3 * ci + 1], cz = pc[3 * ci + 2];
            const float dx = __fadd_rn(cx, -tx);
            const float dy = __fadd_rn(cy, -ty);
            const float dz = __fadd_rn(cz, -tz);
            const float n2 = __fadd_rn(__fadd_rn(__fmul_rn(dx, dx), __fmul_rn(dy, dy)),
                                       __fmul_rn(dz, dz));
            const float nrm = __fadd_rn(__fsqrt_rn(n2), 1e-8f);
            const float A0 = __fdiv_rn(dx, nrm);
            const float A1 = __fdiv_rn(dy, nrm);
            const float A2 = __fdiv_rn(dz, nrm);
            const float B  = __fadd_rn(__fadd_rn(__fmul_rn(A0, cx), __fmul_rn(A1, cy)),
                                       __fmul_rn(A2, cz));
            if (!empty) {
                if (rank == 0) {
                    const size_t oa = (size_t)iter * M * 3 + (size_t)m * 3;
                    outA[oa + 0] = A0; outA[oa + 1] = A1; outA[oa + 2] = A2;
                    outB[(size_t)iter * M + m] = B;
                }
                s_pl[0] = A0; s_pl[1] = A1; s_pl[2] = A2; s_pl[3] = B;
            } else {
                // Empty survivor set: (a,b) constant for all remaining iterations.
                if (rank == 0) {
                    for (int k = iter; k < ITERS; ++k) {
                        const size_t oa = (size_t)k * M * 3 + (size_t)m * 3;
                        outA[oa + 0] = A0; outA[oa + 1] = A1; outA[oa + 2] = A2;
                        outB[(size_t)k * M + m] = B;
                    }
                }
                s_done = 1;
            }
        }
        __syncthreads();

        if (s_done) break;   // merged state identical on both ranks -> same decision

        a0 = s_pl[0]; a1 = s_pl[1]; a2 = s_pl[2]; bpl = s_pl[3];
        if (iter >= 1) count = s_cursor;
        __syncthreads();   // protect s_cursor / s_done / s_pl against next-iter reset
    }
}

extern "C" void kernel_launch(void* const* d_in, const int* in_sizes, int n_in,
                              void* d_out, int out_size)
{
    const float* pc = (const float*)d_in[0];
    const float* tg = (const float*)d_in[1];
    int szp = in_sizes[0], szt = in_sizes[1];
    if (szp < szt) {  // defensive: pointcloud is the larger input
        const float* t = pc; pc = tg; tg = t;
        int s = szp; szp = szt; szt = s;
    }
    const int N = szp / 3;
    const int M = szt / 3;
    cpc_kernel<<<M * CLUS, BLK>>>(pc, tg, (float*)d_out, N, M);
}

// round 5
// speedup vs baseline: 1.9098x; 1.4721x over previous
#include <cuda_runtime.h>
#include <cooperative_groups.h>
#include <cstdint>
#include <cstddef>

namespace cg = cooperative_groups;

#define ITERS   50
#define NCAP    200000
#define MCAP    256
#define BLK     512
#define NWARP   (BLK / 32)
#define CLUS    2
// Per-rank survivor capacity: ceil(ceil(200000/128)/32)*16 chunks * 128 = 100352
#define REGION  100352

// Ping-pong survivor lists, one region per (target, cluster-rank).
// Each symbol: 256 * 2 * 100352 * 16B = 822,083,584 bytes (< 2^31 per symbol).
__device__ float4 g_listA[MCAP][CLUS][REGION];
__device__ float4 g_listB[MCAP][CLUS][REGION];

__device__ __forceinline__ void argmin_merge(float& bd, int& bi, float d, int i)
{
    if (d < bd || (d == bd && i < bi)) { bd = d; bi = i; }
}

__global__ void __cluster_dims__(CLUS, 1, 1) __launch_bounds__(BLK, 3)
cpc_kernel(const float* __restrict__ pc, const float* __restrict__ tg,
           float* __restrict__ out, int N, int M)
{
    cg::cluster_group cl = cg::this_cluster();
    const int rank = (int)cl.block_rank();
    const int m    = blockIdx.x / CLUS;
    const int tid  = threadIdx.x;
    const int lane = tid & 31;
    const int warp = tid >> 5;

    __shared__ float  s_rd[NWARP];
    __shared__ int    s_ri[NWARP];
    __shared__ float  s_pl[4];      // a0, a1, a2, b
    __shared__ int    s_cursor;
    __shared__ int    s_done;
    __shared__ float2 s_mail[2];    // double-buffered {best_d, best_i bits} mailbox

    const float tx = tg[3 * m + 0];
    const float ty = tg[3 * m + 1];
    const float tz = tg[3 * m + 2];
    // t2 = sum(targets*targets, axis=1): plain mul + sequential add (XLA reduce)
    const float t2 = __fadd_rn(__fadd_rn(__fmul_rn(tx, tx), __fmul_rn(ty, ty)),
                               __fmul_rn(tz, tz));

    float a0 = 0.f, a1 = 0.f, a2 = 0.f, bpl = 0.f;   // current plane
    int   count = N;                                  // elements in my source

    float* outA = out;                                  // [ITERS][M][3]
    float* outB = out + (size_t)ITERS * (size_t)M * 3;  // [ITERS][M]

    for (int iter = 0; iter < ITERS; ++iter) {
        if (tid == 0) { s_cursor = 0; s_done = 0; }
        __syncthreads();

        float bd = __int_as_float(0x7f800000);  // +inf
        int   bi = 0x7fffffff;

        const bool havePlane = (iter >= 1);
        // dst for iter k (k>=1): odd -> B, even -> A. src for k>=2 is the other.
        float4* dst = nullptr;
        if (iter >= 1) dst = (iter & 1) ? g_listB[m][rank] : g_listA[m][rank];

        if (iter < 2) {
            // Source = raw pointcloud; interleaved chunk stripes across cluster ranks.
            for (int base = (warp + rank * NWARP) * 128; base < count;
                 base += CLUS * NWARP * 128) {
                float4   v[4];
                unsigned kmask[4];
                bool     kp[4];
                int tot = 0;
                // Phase 1: issue ALL loads up front (MLP=12) — clamped index,
                // no divergent guard, so ptxas can front-batch the LDGs.
                #pragma unroll
                for (int s = 0; s < 4; ++s) {
                    const int i  = base + s * 32 + lane;
                    const int ic = (i < count) ? i : (count - 1);
                    v[s] = make_float4(pc[3 * ic], pc[3 * ic + 1], pc[3 * ic + 2],
                                       __int_as_float(i));
                }
                // Phase 2: predicate + ballot + argmin (no memory waits inside).
                #pragma unroll
                for (int s = 0; s < 4; ++s) {
                    const int i = __float_as_int(v[s].w);
                    bool keep = (i < count);
                    if (keep && havePlane) {
                        const float da = __fmaf_rn(a2, v[s].z,
                                         __fmaf_rn(a1, v[s].y, __fmul_rn(a0, v[s].x)));
                        keep = (__fadd_rn(da, -bpl) < -1e-6f);
                    }
                    kp[s] = keep;
                    kmask[s] = __ballot_sync(0xffffffffu, keep);
                    tot += __popc(kmask[s]);
                    if (keep) {
                        const float p2 = __fadd_rn(__fadd_rn(__fmul_rn(v[s].x, v[s].x),
                                                             __fmul_rn(v[s].y, v[s].y)),
                                                   __fmul_rn(v[s].z, v[s].z));
                        const float dt = __fmaf_rn(tz, v[s].z,
                                         __fmaf_rn(ty, v[s].y, __fmul_rn(tx, v[s].x)));
                        const float d2 = __fadd_rn(__fadd_rn(t2, p2), __fmul_rn(-2.f, dt));
                        argmin_merge(bd, bi, d2, i);
                    }
                }
                if (dst) {
                    int wbase = 0;
                    if (lane == 0 && tot) wbase = atomicAdd(&s_cursor, tot);
                    wbase = __shfl_sync(0xffffffffu, wbase, 0);
                    int off = 0;
                    #pragma unroll
                    for (int s = 0; s < 4; ++s) {
                        const unsigned mk = kmask[s];
                        if (kp[s]) {
                            const int pos = wbase + off + __popc(mk & ((1u << lane) - 1u));
                            dst[pos] = v[s];
                        }
                        off += __popc(mk);
                    }
                }
            }
        } else {
            // Source = my rank's compacted list from the previous iteration.
            const float4* src = (iter & 1) ? g_listA[m][rank] : g_listB[m][rank];
            for (int base = warp * 128; base < count; base += NWARP * 128) {
                float4   v[4];
                unsigned kmask[4];
                bool     kp[4];
                bool     vl[4];
                int tot = 0;
                // Phase 1: issue ALL loads up front (MLP=4), clamped index.
                #pragma unroll
                for (int s = 0; s < 4; ++s) {
                    const int i  = base + s * 32 + lane;
                    vl[s] = (i < count);
                    const int ic = vl[s] ? i : (count - 1);
                    v[s] = src[ic];
                }
                // Phase 2: predicate + ballot + argmin.
                #pragma unroll
                for (int s = 0; s < 4; ++s) {
                    bool keep = vl[s];
                    if (keep) {
                        const float da = __fmaf_rn(a2, v[s].z,
                                         __fmaf_rn(a1, v[s].y, __fmul_rn(a0, v[s].x)));
                        keep = (__fadd_rn(da, -bpl) < -1e-6f);
                    }
                    kp[s] = keep;
                    kmask[s] = __ballot_sync(0xffffffffu, keep);
                    tot += __popc(kmask[s]);
                    if (keep) {
                        const float p2 = __fadd_rn(__fadd_rn(__fmul_rn(v[s].x, v[s].x),
                                                             __fmul_rn(v[s].y, v[s].y)),
                                                   __fmul_rn(v[s].z, v[s].z));
                        const float dt = __fmaf_rn(tz, v[s].z,
                                         __fmaf_rn(ty, v[s].y, __fmul_rn(tx, v[s].x)));
                        const float d2 = __fadd_rn(__fadd_rn(t2, p2), __fmul_rn(-2.f, dt));
                        argmin_merge(bd, bi, d2, __float_as_int(v[s].w));
                    }
                }
                {
                    int wbase = 0;
                    if (lane == 0 && tot) wbase = atomicAdd(&s_cursor, tot);
                    wbase = __shfl_sync(0xffffffffu, wbase, 0);
                    int off = 0;
                    #pragma unroll
                    for (int s = 0; s < 4; ++s) {
                        const unsigned mk = kmask[s];
                        if (kp[s]) {
                            const int pos = wbase + off + __popc(mk & ((1u << lane) - 1u));
                            dst[pos] = v[s];
                        }
                        off += __popc(mk);
                    }
                }
            }
        }
        __syncthreads();

        // Block argmin reduction (warp shuffle tree, lowest-original-index tie-break)
        #pragma unroll
        for (int o = 16; o; o >>= 1) {
            const float od = __shfl_down_sync(0xffffffffu, bd, o);
            const int   oi = __shfl_down_sync(0xffffffffu, bi, o);
            argmin_merge(bd, bi, od, oi);
        }
        if (lane == 0) { s_rd[warp] = bd; s_ri[warp] = bi; }
        __syncthreads();

        const int buf = iter & 1;
        if (tid < 32) {
            bd = (lane < NWARP) ? s_rd[lane] : __int_as_float(0x7f800000);
            bi = (lane < NWARP) ? s_ri[lane] : 0x7fffffff;
            #pragma unroll
            for (int o = 16; o; o >>= 1) {
                const float od = __shfl_down_sync(0xffffffffu, bd, o);
                const int   oi = __shfl_down_sync(0xffffffffu, bi, o);
                argmin_merge(bd, bi, od, oi);
            }
            if (lane == 0) s_mail[buf] = make_float2(bd, __int_as_float(bi));
        }

        // Cluster-wide exchange of per-rank argmin. barrier.cluster orders the
        // smem write above against the peer's DSMEM read below. Double-buffered
        // mailbox -> a single cluster.sync per iteration is race-free.
        cl.sync();

        if (tid == 0) {
            const float2 ov = s_mail[buf];
            const float2* pmail = cl.map_shared_rank((const float2*)s_mail, rank ^ 1);
            const float2 pv = pmail[buf];
            float fbd = ov.x;  int fbi = __float_as_int(ov.y);
            argmin_merge(fbd, fbi, pv.x, __float_as_int(pv.y));

            const bool empty = (fbi == 0x7fffffff);   // all-inf -> jnp.argmin = 0
            const int  ci = empty ? 0 : fbi;
            const float cx = pc[3 * ci], cy = pc[3 * ci + 1], cz = pc[3 * ci + 2];
            const float dx = __fadd_rn(cx, -tx);
            const float dy = __fadd_rn(cy, -ty);
            const float dz = __fadd_rn(cz, -tz);
            const float n2 = __fadd_rn(__fadd_rn(__fmul_rn(dx, dx), __fmul_rn(dy, dy)),
                                       __fmul_rn(dz, dz));
            const float nrm = __fadd_rn(__fsqrt_rn(n2), 1e-8f);
            const float A0 = __fdiv_rn(dx, nrm);
            const float A1 = __fdiv_rn(dy, nrm);
            const float A2 = __fdiv_rn(dz, nrm);
            const float B  = __fadd_rn(__fadd_rn(__fmul_rn(A0, cx), __fmul_rn(A1, cy)),
                                       __fmul_rn(A2, cz));
            if (!empty) {
                if (rank == 0) {
                    const size_t oa = (size_t)iter * M * 3 + (size_t)m * 3;
                    outA[oa + 0] = A0; outA[oa + 1] = A1; outA[oa + 2] = A2;
                    outB[(size_t)iter * M + m] = B;
                }
                s_pl[0] = A0; s_pl[1] = A1; s_pl[2] = A2; s_pl[3] = B;
            } else {
                // Empty survivor set: (a,b) constant for all remaining iterations.
                if (rank == 0) {
                    for (int k = iter; k < ITERS; ++k) {
                        const size_t oa = (size_t)k * M * 3 + (size_t)m * 3;
                        outA[oa + 0] = A0; outA[oa + 1] = A1; outA[oa + 2] = A2;
                        outB[(size_t)k * M + m] = B;
                    }
                }
                s_done = 1;
            }
        }
        __syncthreads();

        if (s_done) break;   // merged state identical on both ranks -> same decision

        a0 = s_pl[0]; a1 = s_pl[1]; a2 = s_pl[2]; bpl = s_pl[3];
        if (iter >= 1) count = s_cursor;
        __syncthreads();   // protect s_cursor / s_done / s_pl against next-iter reset
    }
}

extern "C" void kernel_launch(void* const* d_in, const int* in_sizes, int n_in,
                              void* d_out, int out_size)
{
    const float* pc = (const float*)d_in[0];
    const float* tg = (const float*)d_in[1];
    int szp = in_sizes[0], szt = in_sizes[1];
    if (szp < szt) {  // defensive: pointcloud is the larger input
        const float* t = pc; pc = tg; tg = t;
        int s = szp; szp = szt; szt = s;
    }
    const int N = szp / 3;
    const int M = szt / 3;
    cpc_kernel<<<M * CLUS, BLK>>>(pc, tg, (float*)d_out, N, M);
}

// round 7
// speedup vs baseline: 2.2333x; 1.1693x over previous
#include <cuda_runtime.h>
#include <cooperative_groups.h>
#include <cstdint>
#include <cstddef>

namespace cg = cooperative_groups;

#define ITERS   50
#define NCAP    200000
#define MCAP    256
#define BLK     512
#define NWARP   (BLK / 32)
#define CLUS    2
// Per-rank survivor capacity: ceil(ceil(200000/128)/32)*16 chunks * 128 = 100352
#define REGION  100352

// Ping-pong survivor INDEX lists, one region per (target, cluster-rank).
// Each symbol: 256 * 2 * 100352 * 4B = 205,520,896 bytes.
__device__ int g_idxA[MCAP][CLUS][REGION];
__device__ int g_idxB[MCAP][CLUS][REGION];

__device__ __forceinline__ void argmin_merge(float& bd, int& bi, float d, int i)
{
    if (d < bd || (d == bd && i < bi)) { bd = d; bi = i; }
}

__global__ void __cluster_dims__(CLUS, 1, 1) __launch_bounds__(BLK, 3)
cpc_kernel(const float* __restrict__ pc, const float* __restrict__ tg,
           float* __restrict__ out, int N, int M)
{
    cg::cluster_group cl = cg::this_cluster();
    const int rank = (int)cl.block_rank();
    const int m    = blockIdx.x / CLUS;
    const int tid  = threadIdx.x;
    const int lane = tid & 31;
    const int warp = tid >> 5;

    __shared__ float  s_rd[NWARP];
    __shared__ int    s_ri[NWARP];
    __shared__ float  s_pl[4];      // a0, a1, a2, b
    __shared__ int    s_cursor;
    __shared__ int    s_done;
    __shared__ float2 s_mail[2];    // double-buffered {best_d, best_i bits} mailbox

    const float tx = tg[3 * m + 0];
    const float ty = tg[3 * m + 1];
    const float tz = tg[3 * m + 2];
    // t2 = sum(targets*targets, axis=1): plain mul + sequential add (XLA reduce)
    const float t2 = __fadd_rn(__fadd_rn(__fmul_rn(tx, tx), __fmul_rn(ty, ty)),
                               __fmul_rn(tz, tz));

    float a0 = 0.f, a1 = 0.f, a2 = 0.f, bpl = 0.f;   // current plane
    int   count = N;                                  // elements in my source

    float* outA = out;                                  // [ITERS][M][3]
    float* outB = out + (size_t)ITERS * (size_t)M * 3;  // [ITERS][M]

    for (int iter = 0; iter < ITERS; ++iter) {
        if (tid == 0) { s_cursor = 0; s_done = 0; }
        __syncthreads();

        float bd = __int_as_float(0x7f800000);  // +inf
        int   bi = 0x7fffffff;

        const bool havePlane = (iter >= 1);
        // dst for iter k (k>=1): odd -> B, even -> A. src for k>=2 is the other.
        int* dst = nullptr;
        if (iter >= 1) dst = (iter & 1) ? g_idxB[m][rank] : g_idxA[m][rank];

        if (iter < 2) {
            // Source = raw pointcloud; interleaved chunk stripes across cluster ranks.
            for (int base = (warp + rank * NWARP) * 128; base < count;
                 base += CLUS * NWARP * 128) {
                float    px[4], py[4], pz[4];
                unsigned kmask[4];
                bool     kp[4];
                int tot = 0;
                // Phase 1: issue ALL loads up front (MLP=12) — clamped index,
                // no divergent guard, so ptxas can front-batch the LDGs.
                #pragma unroll
                for (int s = 0; s < 4; ++s) {
                    const int i  = base + s * 32 + lane;
                    const int ic = (i < count) ? i : (count - 1);
                    px[s] = pc[3 * ic];  py[s] = pc[3 * ic + 1];  pz[s] = pc[3 * ic + 2];
                }
                // Phase 2: predicate + ballot + argmin (no memory waits inside).
                #pragma unroll
                for (int s = 0; s < 4; ++s) {
                    const int i = base + s * 32 + lane;
                    bool keep = (i < count);
                    if (keep && havePlane) {
                        const float da = __fmaf_rn(a2, pz[s],
                                         __fmaf_rn(a1, py[s], __fmul_rn(a0, px[s])));
                        keep = (__fadd_rn(da, -bpl) < -1e-6f);
                    }
                    kp[s] = keep;
                    kmask[s] = __ballot_sync(0xffffffffu, keep);
                    tot += __popc(kmask[s]);
                    if (keep) {
                        const float p2 = __fadd_rn(__fadd_rn(__fmul_rn(px[s], px[s]),
                                                             __fmul_rn(py[s], py[s])),
                                                   __fmul_rn(pz[s], pz[s]));
                        const float dt = __fmaf_rn(tz, pz[s],
                                         __fmaf_rn(ty, py[s], __fmul_rn(tx, px[s])));
                        const float d2 = __fadd_rn(__fadd_rn(t2, p2), __fmul_rn(-2.f, dt));
                        argmin_merge(bd, bi, d2, i);
                    }
                }
                if (dst) {
                    int wbase = 0;
                    if (lane == 0 && tot) wbase = atomicAdd(&s_cursor, tot);
                    wbase = __shfl_sync(0xffffffffu, wbase, 0);
                    int off = 0;
                    #pragma unroll
                    for (int s = 0; s < 4; ++s) {
                        const unsigned mk = kmask[s];
                        if (kp[s]) {
                            const int pos = wbase + off + __popc(mk & ((1u << lane) - 1u));
                            dst[pos] = base + s * 32 + lane;
                        }
                        off += __popc(mk);
                    }
                }
            }
        } else {
            // Source = my rank's compacted index list from the previous iteration.
            const int* src = (iter & 1) ? g_idxA[m][rank] : g_idxB[m][rank];
            for (int base = warp * 128; base < count; base += NWARP * 128) {
                int      ix[4];
                float    px[4], py[4], pz[4];
                unsigned kmask[4];
                bool     kp[4];
                bool     vl[4];
                int tot = 0;
                // Phase 1a: load ALL 4 indices first (MLP=4, clamped).
                #pragma unroll
                for (int s = 0; s < 4; ++s) {
                    const int i  = base + s * 32 + lane;
                    vl[s] = (i < count);
                    const int ic = vl[s] ? i : (count - 1);
                    ix[s] = src[ic];
                }
                // Phase 1b: issue ALL 12 xyz gathers (MLP=12, L2-resident pc).
                #pragma unroll
                for (int s = 0; s < 4; ++s) {
                    const int p3 = 3 * ix[s];
                    px[s] = pc[p3];  py[s] = pc[p3 + 1];  pz[s] = pc[p3 + 2];
                }
                // Phase 2: predicate + ballot + argmin.
                #pragma unroll
                for (int s = 0; s < 4; ++s) {
                    bool keep = vl[s];
                    if (keep) {
                        const float da = __fmaf_rn(a2, pz[s],
                                         __fmaf_rn(a1, py[s], __fmul_rn(a0, px[s])));
                        keep = (__fadd_rn(da, -bpl) < -1e-6f);
                    }
                    kp[s] = keep;
                    kmask[s] = __ballot_sync(0xffffffffu, keep);
                    tot += __popc(kmask[s]);
                    if (keep) {
                        const float p2 = __fadd_rn(__fadd_rn(__fmul_rn(px[s], px[s]),
                                                             __fmul_rn(py[s], py[s])),
                                                   __fmul_rn(pz[s], pz[s]));
                        const float dt = __fmaf_rn(tz, pz[s],
                                         __fmaf_rn(ty, py[s], __fmul_rn(tx, px[s])));
                        const float d2 = __fadd_rn(__fadd_rn(t2, p2), __fmul_rn(-2.f, dt));
                        argmin_merge(bd, bi, d2, ix[s]);
                    }
                }
                {
                    int wbase = 0;
                    if (lane == 0 && tot) wbase = atomicAdd(&s_cursor, tot);
                    wbase = __shfl_sync(0xffffffffu, wbase, 0);
                    int off = 0;
                    #pragma unroll
                    for (int s = 0; s < 4; ++s) {
                        const unsigned mk = kmask[s];
                        if (kp[s]) {
                            const int pos = wbase + off + __popc(mk & ((1u << lane) - 1u));
                            dst[pos] = ix[s];
                        }
                        off += __popc(mk);
                    }
                }
            }
        }
        __syncthreads();

        // Block argmin reduction (warp shuffle tree, lowest-original-index tie-break)
        #pragma unroll
        for (int o = 16; o; o >>= 1) {
            const float od = __shfl_down_sync(0xffffffffu, bd, o);
            const int   oi = __shfl_down_sync(0xffffffffu, bi, o);
            argmin_merge(bd, bi, od, oi);
        }
        if (lane == 0) { s_rd[warp] = bd; s_ri[warp] = bi; }
        __syncthreads();

        const int buf = iter & 1;
        if (tid < 32) {
            bd = (lane < NWARP) ? s_rd[lane] : __int_as_float(0x7f800000);
            bi = (lane < NWARP) ? s_ri[lane] : 0x7fffffff;
            #pragma unroll
            for (int o = 16; o; o >>= 1) {
                const float od = __shfl_down_sync(0xffffffffu, bd, o);
                const int   oi = __shfl_down_sync(0xffffffffu, bi, o);
                argmin_merge(bd, bi, od, oi);
            }
            if (lane == 0) s_mail[buf] = make_float2(bd, __int_as_float(bi));
        }

        // Cluster-wide exchange of per-rank argmin. barrier.cluster orders the
        // smem write above against the peer's DSMEM read below. Double-buffered
        // mailbox -> a single cluster.sync per iteration is race-free.
        cl.sync();

        if (tid == 0) {
            const float2 ov = s_mail[buf];
            const float2* pmail = cl.map_shared_rank((const float2*)s_mail, rank ^ 1);
            const float2 pv = pmail[buf];
            float fbd = ov.x;  int fbi = __float_as_int(ov.y);
            argmin_merge(fbd, fbi, pv.x, __float_as_int(pv.y));

            const bool empty = (fbi == 0x7fffffff);   // all-inf -> jnp.argmin = 0
            const int  ci = empty ? 0 : fbi;
            const float cx = pc[3 * ci], cy = pc[3 * ci + 1], cz = pc[3 * ci + 2];
            const float dx = __fadd_rn(cx, -tx);
            const float dy = __fadd_rn(cy, -ty);
            const float dz = __fadd_rn(cz, -tz);
            const float n2 = __fadd_rn(__fadd_rn(__fmul_rn(dx, dx), __fmul_rn(dy, dy)),
                                       __fmul_rn(dz, dz));
            const float nrm = __fadd_rn(__fsqrt_rn(n2), 1e-8f);
            const float A0 = __fdiv_rn(dx, nrm);
            const float A1 = __fdiv_rn(dy, nrm);
            const float A2 = __fdiv_rn(dz, nrm);
            const float B  = __fadd_rn(__fadd_rn(__fmul_rn(A0, cx), __fmul_rn(A1, cy)),
                                       __fmul_rn(A2, cz));
            if (!empty) {
                if (rank == 0) {
                    const size_t oa = (size_t)iter * M * 3 + (size_t)m * 3;
                    outA[oa + 0] = A0; outA[oa + 1] = A1; outA[oa + 2] = A2;
                    outB[(size_t)iter * M + m] = B;
                }
                s_pl[0] = A0; s_pl[1] = A1; s_pl[2] = A2; s_pl[3] = B;
            } else {
                // Empty survivor set: (a,b) constant for all remaining iterations.
                if (rank == 0) {
                    for (int k = iter; k < ITERS; ++k) {
                        const size_t oa = (size_t)k * M * 3 + (size_t)m * 3;
                        outA[oa + 0] = A0; outA[oa + 1] = A1; outA[oa + 2] = A2;
                        outB[(size_t)k * M + m] = B;
                    }
                }
                s_done = 1;
            }
        }
        __syncthreads();

        if (s_done) break;   // merged state identical on both ranks -> same decision

        a0 = s_pl[0]; a1 = s_pl[1]; a2 = s_pl[2]; bpl = s_pl[3];
        if (iter >= 1) count = s_cursor;
        __syncthreads();   // protect s_cursor / s_done / s_pl against next-iter reset
    }
}

extern "C" void kernel_launch(void* const* d_in, const int* in_sizes, int n_in,
                              void* d_out, int out_size)
{
    const float* pc = (const float*)d_in[0];
    const float* tg = (const float*)d_in[1];
    int szp = in_sizes[0], szt = in_sizes[1];
    if (szp < szt) {  // defensive: pointcloud is the larger input
        const float* t = pc; pc = tg; tg = t;
        int s = szp; szp = szt; szt = s;
    }
    const int N = szp / 3;
    const int M = szt / 3;
    cpc_kernel<<<M * CLUS, BLK>>>(pc, tg, (float*)d_out, N, M);
}